// round 10
// baseline (speedup 1.0000x reference)
#include <cuda_runtime.h>
#include <cuda_fp16.h>
#include <cstdint>

#define NN    8192
#define NH    4
#define DH    16
#define NEDGE 262144
#define TE    (NEDGE + NN)

// ---------------- scratch ----------------
__device__ __half g_hcatH[NN * 320];    // [x(256) | attn(64)] f16 single copy
__device__ __half g_t2H[NN * 256];      // t2 f16
__device__ __half g_Bc[192 * 256];      // combined qkv weights, plain f16
__device__ __half g_Bw1[256 * 320];     // folded w1, plain f16
__device__ __half g_Bw2[256 * 256];
__device__ __half g_Bw3[64 * 256];
__device__ float g_bc[192];             // combined qkv bias
__device__ float g_cvec[256];           // opb @ w1_bot (pre-aggregation constant)
__device__ float g_zero[256];           // stays 0
__device__ __half g_t1h[NN * 256];
__device__ int   g_deg[NN];             // zero at entry; k_scan re-zeroes for replay
__device__ int   g_rowptr[NN + 1];
__device__ int   g_cursor[NN];
__device__ int   g_col[TE];
__device__ float g_dinv[NN];
__device__ __half g_Qh[NH * NN * DH];
__device__ __half g_Kh[NH * NN * DH];
__device__ __half g_Vh[NH * NN * DH];

__device__ __forceinline__ uint32_t ex2h2(uint32_t h) {
    uint32_t r;
    asm("ex2.approx.f16x2 %0, %1;" : "=r"(r) : "r"(h));
    return r;
}

// ---------------- mega prep ----------------
// blocks: [0,2048) x | [2048,2304) w1 | [2304,2560) w2 | [2560,2624) w3
//         [2624,2816) Wc | [2816,2880) Wb | [2880,2882) biases | [2882,3138) edge count
__global__ void __launch_bounds__(256) prep(const float* __restrict__ x,
                                            const float* __restrict__ w1,
                                            const float* __restrict__ w2,
                                            const float* __restrict__ w3,
                                            const float* __restrict__ pe_w,
                                            const float* __restrict__ ipw,
                                            const float* __restrict__ opw,
                                            const float* __restrict__ opb,
                                            const float* __restrict__ pe_b,
                                            const float* __restrict__ ipb,
                                            const int* __restrict__ ei)
{
    const int b = blockIdx.x, t = threadIdx.x;
    if (b < 2048) {
        int idx = b * 256 + t;                 // NN*64
        int m = idx >> 6, kk = (idx & 63) * 4;
        float4 v = *(const float4*)&x[(size_t)m * 256 + kk];
        __half2 h0 = __floats2half2_rn(v.x, v.y);
        __half2 h1 = __floats2half2_rn(v.z, v.w);
        __half2* dst = (__half2*)&g_hcatH[(size_t)m * 320 + kk];
        dst[0] = h0; dst[1] = h1;
    } else if (b < 2304) {
        int idx = (b - 2048) * 256 + t;
        int k = idx >> 8, n = idx & 255;
        g_Bw1[n * 320 + k] = __float2half(w1[k * 256 + n]);
    } else if (b < 2560) {
        int idx = (b - 2304) * 256 + t;
        int k = idx >> 8, n = idx & 255;
        g_Bw2[n * 256 + k] = __float2half(w2[k * 256 + n]);
    } else if (b < 2624) {
        int idx = (b - 2560) * 256 + t;
        int k = idx >> 6, n = idx & 63;
        g_Bw3[n * 256 + k] = __float2half(w3[k * 64 + n]);
    } else if (b < 2816) {                     // Wc = pe_w @ ipw^T
        int idx = (b - 2624) * 256 + t;
        int n = idx >> 8, k = idx & 255;
        float s = 0.f;
#pragma unroll 8
        for (int d = 0; d < 64; d++)
            s = fmaf(ipw[n * 64 + d], pe_w[k * 64 + d], s);
        g_Bc[n * 256 + k] = __float2half(s);
    } else if (b < 2880) {                     // Wb = opw^T @ w1_bot
        int idx = (b - 2816) * 256 + t;
        int d = idx >> 8, n = idx & 255;
        float s = 0.f;
#pragma unroll 8
        for (int j = 0; j < 64; j++)
            s = fmaf(opw[j * 64 + d], w1[(256 + j) * 256 + n], s);
        g_Bw1[n * 320 + 256 + d] = __float2half(s);
    } else if (b < 2882) {
        int i = (b - 2880) * 256 + t;
        if (i < 256) {                         // cvec = opb @ w1_bot
            float s = 0.f;
#pragma unroll 8
            for (int j = 0; j < 64; j++)
                s = fmaf(opb[j], w1[(256 + j) * 256 + i], s);
            g_cvec[i] = s;
        } else if (i < 448) {                  // bc = pe_b @ ipw^T + ipb
            int n = i - 256;
            float s = ipb[n];
#pragma unroll 8
            for (int d = 0; d < 64; d++)
                s = fmaf(ipw[n * 64 + d], pe_b[d], s);
            g_bc[n] = s;
        }
    } else {                                   // edge degree count, 4 edges/thread
        int e4 = ((b - 2882) * 256 + t) * 4;
        int4 d = *(const int4*)&ei[NEDGE + e4];
        atomicAdd(&g_deg[d.x], 1);
        atomicAdd(&g_deg[d.y], 1);
        atomicAdd(&g_deg[d.z], 1);
        atomicAdd(&g_deg[d.w], 1);
    }
}

// ---------------- plain f16 tensor-core GEMM ----------------
// C[M,N] = A[M,K] @ B[N,K]^T.
// EPI: 0 = f16 C (+bias), 2 = QKV f16 (+bias, Q scaled)
template<int BM, int EPI>
__global__ void __launch_bounds__(256) gemm_mma(
    const __half* __restrict__ A, const __half* __restrict__ B,
    const float* __restrict__ bias, void* __restrict__ outp,
    int K, int lda, int ldc,
    __half* __restrict__ Qh, __half* __restrict__ Kh, __half* __restrict__ Vh)
{
    constexpr int NWN  = (BM == 128) ? 2 : 4;
    constexpr int WN   = 64 / NWN;
    constexpr int NT   = WN / 8;
    constexpr int AREP = BM / 64;

    __shared__ __half As[2][BM * 40];
    __shared__ __half Bs[2][64 * 40];

    const int t = threadIdx.x, warp = t >> 5, lane = t & 31;
    const int wm = warp / NWN, wn = warp % NWN;
    const int bm = blockIdx.x * BM, bn = blockIdx.y * 64;

    float acc[2][NT][4];
#pragma unroll
    for (int i = 0; i < 2; i++)
#pragma unroll
        for (int j = 0; j < NT; j++)
#pragma unroll
            for (int q = 0; q < 4; q++) acc[i][j][q] = 0.f;

    const int brow = t >> 2, bcg = t & 3;
#pragma unroll
    for (int i = 0; i < AREP; i++) {
        int idx = t + i * 256, row = idx >> 2, cg = idx & 3;
        *(uint4*)&As[0][row * 40 + cg * 8] =
            *(const uint4*)&A[(size_t)(bm + row) * lda + cg * 8];
    }
    *(uint4*)&Bs[0][brow * 40 + bcg * 8] =
        *(const uint4*)&B[(size_t)(bn + brow) * K + bcg * 8];
    __syncthreads();

    const int nk = K >> 5;
    int buf = 0;
    for (int kc = 0; kc < nk; kc++) {
        uint4 pa[AREP], pb;
        const bool more = (kc + 1 < nk);
        if (more) {
            int k0 = (kc + 1) << 5;
#pragma unroll
            for (int i = 0; i < AREP; i++) {
                int idx = t + i * 256, row = idx >> 2, cg = idx & 3;
                pa[i] = *(const uint4*)&A[(size_t)(bm + row) * lda + k0 + cg * 8];
            }
            pb = *(const uint4*)&B[(size_t)(bn + brow) * K + k0 + bcg * 8];
        }

#pragma unroll
        for (int kk = 0; kk < 2; kk++) {
            uint32_t af[2][4];
#pragma unroll
            for (int mt = 0; mt < 2; mt++) {
                uint32_t a = (uint32_t)__cvta_generic_to_shared(
                    &As[buf][(wm * 32 + mt * 16 + (lane & 15)) * 40 + kk * 16 + (lane >> 4) * 8]);
                asm volatile("ldmatrix.sync.aligned.m8n8.x4.shared.b16 {%0,%1,%2,%3}, [%4];"
                             : "=r"(af[mt][0]), "=r"(af[mt][1]), "=r"(af[mt][2]), "=r"(af[mt][3])
                             : "r"(a));
            }
            uint32_t bfg[NT][2];
#pragma unroll
            for (int p = 0; p < NT / 2; p++) {
                uint32_t a = (uint32_t)__cvta_generic_to_shared(
                    &Bs[buf][(wn * WN + (2 * p + (lane >> 4)) * 8 + (lane & 7)) * 40 +
                             kk * 16 + ((lane >> 3) & 1) * 8]);
                asm volatile("ldmatrix.sync.aligned.m8n8.x4.shared.b16 {%0,%1,%2,%3}, [%4];"
                             : "=r"(bfg[2 * p][0]), "=r"(bfg[2 * p][1]),
                               "=r"(bfg[2 * p + 1][0]), "=r"(bfg[2 * p + 1][1])
                             : "r"(a));
            }
#pragma unroll
            for (int mt = 0; mt < 2; mt++)
#pragma unroll
                for (int nt = 0; nt < NT; nt++)
                    asm volatile("mma.sync.aligned.m16n8k16.row.col.f32.f16.f16.f32 "
                                 "{%0,%1,%2,%3}, {%4,%5,%6,%7}, {%8,%9}, {%0,%1,%2,%3};"
                                 : "+f"(acc[mt][nt][0]), "+f"(acc[mt][nt][1]),
                                   "+f"(acc[mt][nt][2]), "+f"(acc[mt][nt][3])
                                 : "r"(af[mt][0]), "r"(af[mt][1]), "r"(af[mt][2]), "r"(af[mt][3]),
                                   "r"(bfg[nt][0]), "r"(bfg[nt][1]));
        }

        if (more) {
#pragma unroll
            for (int i = 0; i < AREP; i++) {
                int idx = t + i * 256, row = idx >> 2, cg = idx & 3;
                *(uint4*)&As[buf ^ 1][row * 40 + cg * 8] = pa[i];
            }
            *(uint4*)&Bs[buf ^ 1][brow * 40 + bcg * 8] = pb;
        }
        __syncthreads();
        buf ^= 1;
    }

#pragma unroll
    for (int nt = 0; nt < NT; nt++) {
        const int col0 = bn + wn * WN + nt * 8 + (lane & 3) * 2;
        float2 bv = make_float2(0.f, 0.f);
        if (bias) bv = *(const float2*)&bias[col0];
#pragma unroll
        for (int mt = 0; mt < 2; mt++) {
            const int r0 = bm + wm * 32 + mt * 16 + (lane >> 2);
            float v00 = acc[mt][nt][0] + bv.x, v01 = acc[mt][nt][1] + bv.y;
            float v10 = acc[mt][nt][2] + bv.x, v11 = acc[mt][nt][3] + bv.y;
            if (EPI == 0) {
                __half* C = (__half*)outp;
                *(__half2*)&C[(size_t)r0 * ldc + col0]       = __floats2half2_rn(v00, v01);
                *(__half2*)&C[(size_t)(r0 + 8) * ldc + col0] = __floats2half2_rn(v10, v11);
            } else {
                int sec = col0 >> 6;
                int h   = (col0 & 63) >> 4;
                int d   = col0 & 15;
                if (sec == 0) {
                    v00 *= 0.36067376022224085f; v01 *= 0.36067376022224085f;
                    v10 *= 0.36067376022224085f; v11 *= 0.36067376022224085f;
                }
                __half* dst = (sec == 0) ? Qh : (sec == 1 ? Kh : Vh);
                *(__half2*)&dst[(((size_t)h * NN + r0) << 4) + d] =
                    __floats2half2_rn(v00, v01);
                *(__half2*)&dst[(((size_t)h * NN + r0 + 8) << 4) + d] =
                    __floats2half2_rn(v10, v11);
            }
        }
    }
}

// ---------------- tensor-core flash attention: f16 QK accum, KTILE=128 ----------------
#define KSTRIDE 24
#define QTILE 128
#define KTILE 128

__global__ void __launch_bounds__(256) attn_mma(const __half* __restrict__ Qh,
                                                const __half* __restrict__ Kh,
                                                const __half* __restrict__ Vh,
                                                __half* __restrict__ hcatH)
{
    __shared__ __half Kt[2][KTILE * KSTRIDE];
    __shared__ __half Vt[2][KTILE * KSTRIDE];
    const int tid  = threadIdx.x;
    const int w    = tid >> 5, lane = tid & 31;
    const int h    = blockIdx.y;
    const int q0   = blockIdx.x * QTILE;
    const int g    = lane >> 2, c = lane & 3;

    uint32_t qa[4];
    {
        const __half* qb = Qh + (((size_t)h * NN + q0 + w * 16) << 4);
        qa[0] = *(const uint32_t*)&qb[(g)     * 16 + 2 * c];
        qa[1] = *(const uint32_t*)&qb[(g + 8) * 16 + 2 * c];
        qa[2] = *(const uint32_t*)&qb[(g)     * 16 + 2 * c + 8];
        qa[3] = *(const uint32_t*)&qb[(g + 8) * 16 + 2 * c + 8];
    }

    float o[3][4];
#pragma unroll
    for (int i = 0; i < 3; i++)
#pragma unroll
        for (int j = 0; j < 4; j++) o[i][j] = 0.f;

    const int lrow = tid >> 2;              // 0..63
    const int lseg = (tid & 3) * 4;
    const __half* Kg = Kh + ((size_t)h * NN << 4);
    const __half* Vg = Vh + ((size_t)h * NN << 4);

    // ones-column constants at Vt cols [16..23]: col16 = 1.0h, rest 0. Never overwritten
    // (mainloop writes cols [0,16) only).
#pragma unroll
    for (int j = 0; j < 4; j++) {
        int idx = tid * 4 + j;              // 0..1023
        int bu = idx >> 9, row = (idx >> 2) & 127, pr = idx & 3;
        *(uint32_t*)&Vt[bu][row * KSTRIDE + 16 + pr * 2] = (pr == 0) ? 0x00003C00u : 0u;
    }

    *(uint2*)&Kt[0][lrow * KSTRIDE + lseg]        = *(const uint2*)&Kg[lrow * 16 + lseg];
    *(uint2*)&Kt[0][(lrow + 64) * KSTRIDE + lseg] = *(const uint2*)&Kg[(lrow + 64) * 16 + lseg];
    *(uint2*)&Vt[0][lrow * KSTRIDE + lseg]        = *(const uint2*)&Vg[lrow * 16 + lseg];
    *(uint2*)&Vt[0][(lrow + 64) * KSTRIDE + lseg] = *(const uint2*)&Vg[(lrow + 64) * 16 + lseg];
    __syncthreads();

    // hoist the constant ones-column B-fragment (identical for every tile/kc)
    uint32_t on0, on1;
    {
        uint32_t a = (uint32_t)__cvta_generic_to_shared(
            &Vt[0][(lane & 15) * KSTRIDE + 16]);
        asm volatile("ldmatrix.sync.aligned.m8n8.x2.trans.shared.b16 {%0,%1}, [%2];"
                     : "=r"(on0), "=r"(on1) : "r"(a));
    }

    int buf = 0;
    for (int kt = 0; kt < NN / KTILE; kt++) {
        uint2 kp0, kp1, vp0, vp1;
        const bool more = (kt + 1 < NN / KTILE);
        if (more) {
            int base = (kt + 1) * KTILE;
            kp0 = *(const uint2*)&Kg[(base + lrow) * 16 + lseg];
            kp1 = *(const uint2*)&Kg[(base + lrow + 64) * 16 + lseg];
            vp0 = *(const uint2*)&Vg[(base + lrow) * 16 + lseg];
            vp1 = *(const uint2*)&Vg[(base + lrow + 64) * 16 + lseg];
        }

        // ---- S = Q@K^T with f16 accumulators: output IS the PV A-fragment (after ex2) ----
        uint32_t ps[16][2];
#pragma unroll
        for (int p = 0; p < 8; p++) {
            uint32_t kb[4];
            uint32_t a = (uint32_t)__cvta_generic_to_shared(
                &Kt[buf][((2 * p + (lane >> 4)) * 8 + (lane & 7)) * KSTRIDE +
                         ((lane >> 3) & 1) * 8]);
            asm volatile("ldmatrix.sync.aligned.m8n8.x4.shared.b16 {%0,%1,%2,%3}, [%4];"
                         : "=r"(kb[0]), "=r"(kb[1]), "=r"(kb[2]), "=r"(kb[3]) : "r"(a));
#pragma unroll
            for (int u = 0; u < 2; u++) {
                uint32_t d0, d1;
                asm volatile("mma.sync.aligned.m16n8k16.row.col.f16.f16.f16.f16 "
                             "{%0,%1}, {%2,%3,%4,%5}, {%6,%7}, {%8,%9};"
                             : "=r"(d0), "=r"(d1)
                             : "r"(qa[0]), "r"(qa[1]), "r"(qa[2]), "r"(qa[3]),
                               "r"(kb[2 * u]), "r"(kb[2 * u + 1]),
                               "r"(0u), "r"(0u));
                ps[2 * p + u][0] = ex2h2(d0);
                ps[2 * p + u][1] = ex2h2(d1);
            }
        }
        // ---- O += P @ [V | ones] ----
#pragma unroll
        for (int kc = 0; kc < 8; kc++) {
            uint32_t vb[4];
            uint32_t a = (uint32_t)__cvta_generic_to_shared(
                &Vt[buf][(kc * 16 + (lane & 15)) * KSTRIDE + ((lane >> 4) & 1) * 8]);
            asm volatile("ldmatrix.sync.aligned.m8n8.x4.trans.shared.b16 {%0,%1,%2,%3}, [%4];"
                         : "=r"(vb[0]), "=r"(vb[1]), "=r"(vb[2]), "=r"(vb[3]) : "r"(a));
#pragma unroll
            for (int dt = 0; dt < 2; dt++)
                asm volatile("mma.sync.aligned.m16n8k16.row.col.f32.f16.f16.f32 "
                             "{%0,%1,%2,%3}, {%4,%5,%6,%7}, {%8,%9}, {%0,%1,%2,%3};"
                             : "+f"(o[dt][0]), "+f"(o[dt][1]), "+f"(o[dt][2]), "+f"(o[dt][3])
                             : "r"(ps[2 * kc][0]), "r"(ps[2 * kc][1]),
                               "r"(ps[2 * kc + 1][0]), "r"(ps[2 * kc + 1][1]),
                               "r"(vb[2 * dt]), "r"(vb[2 * dt + 1]));
            asm volatile("mma.sync.aligned.m16n8k16.row.col.f32.f16.f16.f32 "
                         "{%0,%1,%2,%3}, {%4,%5,%6,%7}, {%8,%9}, {%0,%1,%2,%3};"
                         : "+f"(o[2][0]), "+f"(o[2][1]), "+f"(o[2][2]), "+f"(o[2][3])
                         : "r"(ps[2 * kc][0]), "r"(ps[2 * kc][1]),
                           "r"(ps[2 * kc + 1][0]), "r"(ps[2 * kc + 1][1]),
                           "r"(on0), "r"(on1));
        }

        if (more) {
            *(uint2*)&Kt[buf ^ 1][lrow * KSTRIDE + lseg]        = kp0;
            *(uint2*)&Kt[buf ^ 1][(lrow + 64) * KSTRIDE + lseg] = kp1;
            *(uint2*)&Vt[buf ^ 1][lrow * KSTRIDE + lseg]        = vp0;
            *(uint2*)&Vt[buf ^ 1][(lrow + 64) * KSTRIDE + lseg] = vp1;
        }
        __syncthreads();
        buf ^= 1;
    }

    // row sums live in the ones-column of the third accumulator, held by c==0 lanes
    const float l0 = __shfl_sync(0xffffffff, o[2][0], lane & ~3);
    const float l1 = __shfl_sync(0xffffffff, o[2][2], lane & ~3);
    const float i0 = 1.f / l0, i1 = 1.f / l1;

    const int qrow = q0 + w * 16 + g;
    const int cb   = 256 + h * 16 + 2 * c;
    *(__half2*)&hcatH[(size_t)qrow * 320 + cb] =
        __floats2half2_rn(o[0][0] * i0, o[0][1] * i0);
    *(__half2*)&hcatH[(size_t)qrow * 320 + cb + 8] =
        __floats2half2_rn(o[1][0] * i0, o[1][1] * i0);
    *(__half2*)&hcatH[(size_t)(qrow + 8) * 320 + cb] =
        __floats2half2_rn(o[0][2] * i1, o[0][3] * i1);
    *(__half2*)&hcatH[(size_t)(qrow + 8) * 320 + cb + 8] =
        __floats2half2_rn(o[1][2] * i1, o[1][3] * i1);
}

// ---------------- CSR scan (deg counted by prep; +1 self loop; reset deg) ----------------
__global__ void __launch_bounds__(1024) k_scan()
{
    __shared__ int wsum[32];
    const int tid = threadIdx.x, lane = tid & 31, wid = tid >> 5;
    const int base = tid * 8;
    int v[8], s = 0;
#pragma unroll
    for (int j = 0; j < 8; j++) {
        v[j] = g_deg[base + j] + 1;
        g_deg[base + j] = 0;
        s += v[j];
    }
    int inc = s;
#pragma unroll
    for (int off = 1; off < 32; off <<= 1) {
        int u = __shfl_up_sync(0xffffffff, inc, off);
        if (lane >= off) inc += u;
    }
    if (lane == 31) wsum[wid] = inc;
    __syncthreads();
    if (wid == 0) {
        int t = wsum[lane];
#pragma unroll
        for (int off = 1; off < 32; off <<= 1) {
            int p = __shfl_up_sync(0xffffffff, t, off);
            if (lane >= off) t += p;
        }
        wsum[lane] = t;
    }
    __syncthreads();
    int run = inc - s + (wid ? wsum[wid - 1] : 0);
#pragma unroll
    for (int j = 0; j < 8; j++) {
        int node = base + j;
        g_rowptr[node] = run;
        g_cursor[node] = run;
        g_dinv[node] = rsqrtf((float)v[j]);
        run += v[j];
    }
    if (tid == 1023) g_rowptr[NN] = run;
}

__global__ void __launch_bounds__(256) k_fill(const int* __restrict__ ei)
{
    int e4 = (blockIdx.x * 256 + threadIdx.x) * 4;
    if (e4 < NEDGE) {
        int4 s = *(const int4*)&ei[e4];
        int4 d = *(const int4*)&ei[NEDGE + e4];
        int p0 = atomicAdd(&g_cursor[d.x], 1);
        int p1 = atomicAdd(&g_cursor[d.y], 1);
        int p2 = atomicAdd(&g_cursor[d.z], 1);
        int p3 = atomicAdd(&g_cursor[d.w], 1);
        g_col[p0] = s.x; g_col[p1] = s.y; g_col[p2] = s.z; g_col[p3] = s.w;
    } else {
        int n = e4 - NEDGE;
#pragma unroll
        for (int j = 0; j < 4; j++) {
            int pos = atomicAdd(&g_cursor[n + j], 1);
            g_col[pos] = n + j;
        }
    }
}

// ---------------- GCN aggregation: out = relu(di*(a + cvec*ws) + b), f16 out ----------------
template<bool RELU>
__global__ void __launch_bounds__(256) agg256(const __half* __restrict__ hw,
                                              const float* __restrict__ bias,
                                              const float* __restrict__ cvec,
                                              __half* __restrict__ outH)
{
    int gwarp = (blockIdx.x * blockDim.x + threadIdx.x) >> 5;
    int node = gwarp >> 1;
    const int lane = threadIdx.x & 31;
    const int c = (gwarp & 1) * 128 + lane * 4;
    const int r0 = g_rowptr[node], r1 = g_rowptr[node + 1];
    const float di = g_dinv[node];

    float a[4] = {0.f, 0.f, 0.f, 0.f};
    float ws = 0.f;
    int sc = g_col[r0];
    for (int e = r0; e < r1; e++) {
        int s = sc;
        if (e + 1 < r1) sc = g_col[e + 1];
        float w = g_dinv[s];
        ws += w;
        uint2 raw = *(const uint2*)&hw[(size_t)s * 256 + c];
        float2 f01 = __half22float2(*(__half2*)&raw.x);
        float2 f23 = __half22float2(*(__half2*)&raw.y);
        a[0] = fmaf(w, f01.x, a[0]); a[1] = fmaf(w, f01.y, a[1]);
        a[2] = fmaf(w, f23.x, a[2]); a[3] = fmaf(w, f23.y, a[3]);
    }
    float o[4];
#pragma unroll
    for (int j = 0; j < 4; j++) {
        o[j] = fmaf(di, fmaf(cvec[c + j], ws, a[j]), bias[c + j]);
        if (RELU) o[j] = fmaxf(o[j], 0.f);
    }
    uint2 st;
    *(__half2*)&st.x = __floats2half2_rn(o[0], o[1]);
    *(__half2*)&st.y = __floats2half2_rn(o[2], o[3]);
    *(uint2*)&outH[(size_t)node * 256 + c] = st;
}

// F=64 final layer, fp32 out
__global__ void __launch_bounds__(256) agg64(const __half* __restrict__ hw,
                                             const float* __restrict__ bias,
                                             float* __restrict__ out)
{
    int node = (blockIdx.x * blockDim.x + threadIdx.x) >> 5;
    const int lane = threadIdx.x & 31;
    const int c = lane * 2;
    const int r0 = g_rowptr[node], r1 = g_rowptr[node + 1];
    const float di = g_dinv[node];

    float ax = 0.f, ay = 0.f;
    int sc = g_col[r0];
    for (int e = r0; e < r1; e++) {
        int s = sc;
        if (e + 1 < r1) sc = g_col[e + 1];
        float w = g_dinv[s];
        float2 f = __half22float2(*(const __half2*)&hw[(size_t)s * 64 + c]);
        ax = fmaf(w, f.x, ax);
        ay = fmaf(w, f.y, ay);
    }
    float2 o;
    o.x = fmaf(di, ax, bias[c]);
    o.y = fmaf(di, ay, bias[c + 1]);
    *(float2*)&out[(size_t)node * 64 + c] = o;
}

// ---------------- launch ----------------
extern "C" void kernel_launch(void* const* d_in, const int* in_sizes, int n_in,
                              void* d_out, int out_size)
{
    const float* x    = (const float*)d_in[0];
    const int*   ei   = (const int*)d_in[1];
    const float* pe_w = (const float*)d_in[2];
    const float* pe_b = (const float*)d_in[3];
    const float* ipw  = (const float*)d_in[4];
    const float* ipb  = (const float*)d_in[5];
    const float* opw  = (const float*)d_in[6];
    const float* opb  = (const float*)d_in[7];
    const float* w1   = (const float*)d_in[8];
    const float* b1   = (const float*)d_in[9];
    const float* w2   = (const float*)d_in[10];
    const float* b2   = (const float*)d_in[11];
    const float* w3   = (const float*)d_in[12];
    const float* b3   = (const float*)d_in[13];
    float* out = (float*)d_out;

    __half *hcatH, *t2H, *Bc, *Bw1, *Bw2, *Bw3, *t1h, *Qh, *Kh, *Vh;
    float *bc, *cvec, *zero;
    cudaGetSymbolAddress((void**)&hcatH, g_hcatH);
    cudaGetSymbolAddress((void**)&t2H,   g_t2H);
    cudaGetSymbolAddress((void**)&Bc,    g_Bc);
    cudaGetSymbolAddress((void**)&Bw1,   g_Bw1);
    cudaGetSymbolAddress((void**)&Bw2,   g_Bw2);
    cudaGetSymbolAddress((void**)&Bw3,   g_Bw3);
    cudaGetSymbolAddress((void**)&Qh,    g_Qh);
    cudaGetSymbolAddress((void**)&Kh,    g_Kh);
    cudaGetSymbolAddress((void**)&Vh,    g_Vh);
    cudaGetSymbolAddress((void**)&t1h,   g_t1h);
    cudaGetSymbolAddress((void**)&bc,    g_bc);
    cudaGetSymbolAddress((void**)&cvec,  g_cvec);
    cudaGetSymbolAddress((void**)&zero,  g_zero);

    prep<<<3138, 256>>>(x, w1, w2, w3, pe_w, ipw, opw, opb, pe_b, ipb, ei);
    k_scan<<<1, 1024>>>();
    k_fill<<<TE / 1024, 256>>>(ei);

    // qkv = x @ Wc + bc -> Q/K/V (f16); reads hcat x-cols (K=256, lda=320)
    gemm_mma<128, 2><<<dim3(NN / 128, 3), 256>>>(hcatH, Bc, bc, nullptr,
                                                 256, 320, 0, Qh, Kh, Vh);
    attn_mma<<<dim3(NN / QTILE, NH), 256>>>(Qh, Kh, Vh, hcatH);

    // GCN stack (out_proj folded into w1; +opb via cvec pre-aggregation)
    gemm_mma<128, 0><<<dim3(NN / 128, 4), 256>>>(hcatH, Bw1, nullptr, t1h,
                                                 320, 320, 256, nullptr, nullptr, nullptr);
    agg256<true><<<NN * 64 / 256, 256>>>(t1h, b1, cvec, t2H);
    gemm_mma<128, 0><<<dim3(NN / 128, 4), 256>>>(t2H, Bw2, nullptr, t1h,
                                                 256, 256, 256, nullptr, nullptr, nullptr);
    agg256<true><<<NN * 64 / 256, 256>>>(t1h, b2, zero, t2H);
    gemm_mma<64, 0><<<dim3(NN / 64, 1), 256>>>(t2H, Bw3, nullptr, t1h,
                                               256, 256, 64, nullptr, nullptr, nullptr);
    agg64<<<NN * 32 / 256, 256>>>(t1h, b3, out);
}

// round 11
// speedup vs baseline: 1.0509x; 1.0509x over previous
#include <cuda_runtime.h>
#include <cuda_fp16.h>
#include <cstdint>

#define NN    8192
#define NH    4
#define DH    16
#define NEDGE 262144
#define TE    (NEDGE + NN)

// ---------------- scratch ----------------
__device__ __half g_hcatH[NN * 320];    // [x(256) | attn(64)] f16 single copy
__device__ __half g_t2H[NN * 256];      // t2 f16
__device__ __half g_Bc[192 * 256];      // combined qkv weights, plain f16
__device__ __half g_Bw1[256 * 320];     // folded w1, plain f16
__device__ __half g_Bw2[256 * 256];
__device__ __half g_Bw3[64 * 256];
__device__ float g_bc[192];             // combined qkv bias
__device__ float g_cvec[256];           // opb @ w1_bot (pre-aggregation constant)
__device__ float g_zero[256];           // stays 0
__device__ __half g_t1h[NN * 256];
__device__ int   g_deg[NN];             // zero at entry; k_scan re-zeroes for replay
__device__ int   g_rowptr[NN + 1];
__device__ int   g_cursor[NN];
__device__ int   g_col[TE];
__device__ float g_dinv[NN];
__device__ __half g_Qh[NH * NN * DH];
__device__ __half g_Kh[NH * NN * DH];
__device__ __half g_Vh[NH * NN * DH];

__device__ __forceinline__ uint32_t ex2h2(uint32_t h) {
    uint32_t r;
    asm("ex2.approx.f16x2 %0, %1;" : "=r"(r) : "r"(h));
    return r;
}

// ---------------- mega prep ----------------
// blocks: [0,2048) x | [2048,2304) w1 | [2304,2560) w2 | [2560,2624) w3
//         [2624,2816) Wc | [2816,2880) Wb | [2880,2882) biases | [2882,3138) edge count
__global__ void __launch_bounds__(256) prep(const float* __restrict__ x,
                                            const float* __restrict__ w1,
                                            const float* __restrict__ w2,
                                            const float* __restrict__ w3,
                                            const float* __restrict__ pe_w,
                                            const float* __restrict__ ipw,
                                            const float* __restrict__ opw,
                                            const float* __restrict__ opb,
                                            const float* __restrict__ pe_b,
                                            const float* __restrict__ ipb,
                                            const int* __restrict__ ei)
{
    const int b = blockIdx.x, t = threadIdx.x;
    if (b < 2048) {
        int idx = b * 256 + t;                 // NN*64
        int m = idx >> 6, kk = (idx & 63) * 4;
        float4 v = *(const float4*)&x[(size_t)m * 256 + kk];
        __half2 h0 = __floats2half2_rn(v.x, v.y);
        __half2 h1 = __floats2half2_rn(v.z, v.w);
        __half2* dst = (__half2*)&g_hcatH[(size_t)m * 320 + kk];
        dst[0] = h0; dst[1] = h1;
    } else if (b < 2304) {
        int idx = (b - 2048) * 256 + t;
        int k = idx >> 8, n = idx & 255;
        g_Bw1[n * 320 + k] = __float2half(w1[k * 256 + n]);
    } else if (b < 2560) {
        int idx = (b - 2304) * 256 + t;
        int k = idx >> 8, n = idx & 255;
        g_Bw2[n * 256 + k] = __float2half(w2[k * 256 + n]);
    } else if (b < 2624) {
        int idx = (b - 2560) * 256 + t;
        int k = idx >> 6, n = idx & 63;
        g_Bw3[n * 256 + k] = __float2half(w3[k * 64 + n]);
    } else if (b < 2816) {                     // Wc = pe_w @ ipw^T
        int idx = (b - 2624) * 256 + t;
        int n = idx >> 8, k = idx & 255;
        float s = 0.f;
#pragma unroll 8
        for (int d = 0; d < 64; d++)
            s = fmaf(ipw[n * 64 + d], pe_w[k * 64 + d], s);
        g_Bc[n * 256 + k] = __float2half(s);
    } else if (b < 2880) {                     // Wb = opw^T @ w1_bot
        int idx = (b - 2816) * 256 + t;
        int d = idx >> 8, n = idx & 255;
        float s = 0.f;
#pragma unroll 8
        for (int j = 0; j < 64; j++)
            s = fmaf(opw[j * 64 + d], w1[(256 + j) * 256 + n], s);
        g_Bw1[n * 320 + 256 + d] = __float2half(s);
    } else if (b < 2882) {
        int i = (b - 2880) * 256 + t;
        if (i < 256) {                         // cvec = opb @ w1_bot
            float s = 0.f;
#pragma unroll 8
            for (int j = 0; j < 64; j++)
                s = fmaf(opb[j], w1[(256 + j) * 256 + i], s);
            g_cvec[i] = s;
        } else if (i < 448) {                  // bc = pe_b @ ipw^T + ipb
            int n = i - 256;
            float s = ipb[n];
#pragma unroll 8
            for (int d = 0; d < 64; d++)
                s = fmaf(ipw[n * 64 + d], pe_b[d], s);
            g_bc[n] = s;
        }
    } else {                                   // edge degree count, 4 edges/thread
        int e4 = ((b - 2882) * 256 + t) * 4;
        int4 d = *(const int4*)&ei[NEDGE + e4];
        atomicAdd(&g_deg[d.x], 1);
        atomicAdd(&g_deg[d.y], 1);
        atomicAdd(&g_deg[d.z], 1);
        atomicAdd(&g_deg[d.w], 1);
    }
}

// ---------------- plain f16 tensor-core GEMM ----------------
// C[M,N] = A[M,K] @ B[N,K]^T.
// EPI: 0 = f16 C (+bias), 2 = QKV f16 (+bias, Q scaled)
template<int BM, int EPI>
__global__ void __launch_bounds__(256) gemm_mma(
    const __half* __restrict__ A, const __half* __restrict__ B,
    const float* __restrict__ bias, void* __restrict__ outp,
    int K, int lda, int ldc,
    __half* __restrict__ Qh, __half* __restrict__ Kh, __half* __restrict__ Vh)
{
    constexpr int NWN  = (BM == 128) ? 2 : 4;
    constexpr int WN   = 64 / NWN;
    constexpr int NT   = WN / 8;
    constexpr int AREP = BM / 64;

    __shared__ __half As[2][BM * 40];
    __shared__ __half Bs[2][64 * 40];

    const int t = threadIdx.x, warp = t >> 5, lane = t & 31;
    const int wm = warp / NWN, wn = warp % NWN;
    const int bm = blockIdx.x * BM, bn = blockIdx.y * 64;

    float acc[2][NT][4];
#pragma unroll
    for (int i = 0; i < 2; i++)
#pragma unroll
        for (int j = 0; j < NT; j++)
#pragma unroll
            for (int q = 0; q < 4; q++) acc[i][j][q] = 0.f;

    const int brow = t >> 2, bcg = t & 3;
#pragma unroll
    for (int i = 0; i < AREP; i++) {
        int idx = t + i * 256, row = idx >> 2, cg = idx & 3;
        *(uint4*)&As[0][row * 40 + cg * 8] =
            *(const uint4*)&A[(size_t)(bm + row) * lda + cg * 8];
    }
    *(uint4*)&Bs[0][brow * 40 + bcg * 8] =
        *(const uint4*)&B[(size_t)(bn + brow) * K + bcg * 8];
    __syncthreads();

    const int nk = K >> 5;
    int buf = 0;
    for (int kc = 0; kc < nk; kc++) {
        uint4 pa[AREP], pb;
        const bool more = (kc + 1 < nk);
        if (more) {
            int k0 = (kc + 1) << 5;
#pragma unroll
            for (int i = 0; i < AREP; i++) {
                int idx = t + i * 256, row = idx >> 2, cg = idx & 3;
                pa[i] = *(const uint4*)&A[(size_t)(bm + row) * lda + k0 + cg * 8];
            }
            pb = *(const uint4*)&B[(size_t)(bn + brow) * K + k0 + bcg * 8];
        }

#pragma unroll
        for (int kk = 0; kk < 2; kk++) {
            uint32_t af[2][4];
#pragma unroll
            for (int mt = 0; mt < 2; mt++) {
                uint32_t a = (uint32_t)__cvta_generic_to_shared(
                    &As[buf][(wm * 32 + mt * 16 + (lane & 15)) * 40 + kk * 16 + (lane >> 4) * 8]);
                asm volatile("ldmatrix.sync.aligned.m8n8.x4.shared.b16 {%0,%1,%2,%3}, [%4];"
                             : "=r"(af[mt][0]), "=r"(af[mt][1]), "=r"(af[mt][2]), "=r"(af[mt][3])
                             : "r"(a));
            }
            uint32_t bfg[NT][2];
#pragma unroll
            for (int p = 0; p < NT / 2; p++) {
                uint32_t a = (uint32_t)__cvta_generic_to_shared(
                    &Bs[buf][(wn * WN + (2 * p + (lane >> 4)) * 8 + (lane & 7)) * 40 +
                             kk * 16 + ((lane >> 3) & 1) * 8]);
                asm volatile("ldmatrix.sync.aligned.m8n8.x4.shared.b16 {%0,%1,%2,%3}, [%4];"
                             : "=r"(bfg[2 * p][0]), "=r"(bfg[2 * p][1]),
                               "=r"(bfg[2 * p + 1][0]), "=r"(bfg[2 * p + 1][1])
                             : "r"(a));
            }
#pragma unroll
            for (int mt = 0; mt < 2; mt++)
#pragma unroll
                for (int nt = 0; nt < NT; nt++)
                    asm volatile("mma.sync.aligned.m16n8k16.row.col.f32.f16.f16.f32 "
                                 "{%0,%1,%2,%3}, {%4,%5,%6,%7}, {%8,%9}, {%0,%1,%2,%3};"
                                 : "+f"(acc[mt][nt][0]), "+f"(acc[mt][nt][1]),
                                   "+f"(acc[mt][nt][2]), "+f"(acc[mt][nt][3])
                                 : "r"(af[mt][0]), "r"(af[mt][1]), "r"(af[mt][2]), "r"(af[mt][3]),
                                   "r"(bfg[nt][0]), "r"(bfg[nt][1]));
        }

        if (more) {
#pragma unroll
            for (int i = 0; i < AREP; i++) {
                int idx = t + i * 256, row = idx >> 2, cg = idx & 3;
                *(uint4*)&As[buf ^ 1][row * 40 + cg * 8] = pa[i];
            }
            *(uint4*)&Bs[buf ^ 1][brow * 40 + bcg * 8] = pb;
        }
        __syncthreads();
        buf ^= 1;
    }

#pragma unroll
    for (int nt = 0; nt < NT; nt++) {
        const int col0 = bn + wn * WN + nt * 8 + (lane & 3) * 2;
        float2 bv = make_float2(0.f, 0.f);
        if (bias) bv = *(const float2*)&bias[col0];
#pragma unroll
        for (int mt = 0; mt < 2; mt++) {
            const int r0 = bm + wm * 32 + mt * 16 + (lane >> 2);
            float v00 = acc[mt][nt][0] + bv.x, v01 = acc[mt][nt][1] + bv.y;
            float v10 = acc[mt][nt][2] + bv.x, v11 = acc[mt][nt][3] + bv.y;
            if (EPI == 0) {
                __half* C = (__half*)outp;
                *(__half2*)&C[(size_t)r0 * ldc + col0]       = __floats2half2_rn(v00, v01);
                *(__half2*)&C[(size_t)(r0 + 8) * ldc + col0] = __floats2half2_rn(v10, v11);
            } else {
                int sec = col0 >> 6;
                int h   = (col0 & 63) >> 4;
                int d   = col0 & 15;
                if (sec == 0) {
                    v00 *= 0.36067376022224085f; v01 *= 0.36067376022224085f;
                    v10 *= 0.36067376022224085f; v11 *= 0.36067376022224085f;
                }
                __half* dst = (sec == 0) ? Qh : (sec == 1 ? Kh : Vh);
                *(__half2*)&dst[(((size_t)h * NN + r0) << 4) + d] =
                    __floats2half2_rn(v00, v01);
                *(__half2*)&dst[(((size_t)h * NN + r0 + 8) << 4) + d] =
                    __floats2half2_rn(v10, v11);
            }
        }
    }
}

// ---------------- tensor-core flash attention: f16 QK accum, KTILE=64 ----------------
#define KSTRIDE 24
#define QTILE 128

__global__ void __launch_bounds__(256) attn_mma(const __half* __restrict__ Qh,
                                                const __half* __restrict__ Kh,
                                                const __half* __restrict__ Vh,
                                                __half* __restrict__ hcatH)
{
    __shared__ __half Kt[2][64 * KSTRIDE];
    __shared__ __half Vt[2][64 * KSTRIDE];
    const int tid  = threadIdx.x;
    const int w    = tid >> 5, lane = tid & 31;
    const int h    = blockIdx.y;
    const int q0   = blockIdx.x * QTILE;
    const int g    = lane >> 2, c = lane & 3;

    uint32_t qa[4];
    {
        const __half* qb = Qh + (((size_t)h * NN + q0 + w * 16) << 4);
        qa[0] = *(const uint32_t*)&qb[(g)     * 16 + 2 * c];
        qa[1] = *(const uint32_t*)&qb[(g + 8) * 16 + 2 * c];
        qa[2] = *(const uint32_t*)&qb[(g)     * 16 + 2 * c + 8];
        qa[3] = *(const uint32_t*)&qb[(g + 8) * 16 + 2 * c + 8];
    }

    float o[3][4];
#pragma unroll
    for (int i = 0; i < 3; i++)
#pragma unroll
        for (int j = 0; j < 4; j++) o[i][j] = 0.f;

    const int lrow = tid >> 2;
    const int lseg = (tid & 3) * 4;
    const __half* Kg = Kh + ((size_t)h * NN << 4);
    const __half* Vg = Vh + ((size_t)h * NN << 4);

    // ones-column constants at Vt cols [16..23]: col16 = 1.0h, rest 0. Never overwritten
    // (mainloop writes cols [0,16) only).
#pragma unroll
    for (int j = 0; j < 2; j++) {
        int idx = tid * 2 + j;
        int bu = idx >> 8, row = (idx >> 2) & 63, pr = idx & 3;
        *(uint32_t*)&Vt[bu][row * KSTRIDE + 16 + pr * 2] = (pr == 0) ? 0x00003C00u : 0u;
    }

    *(uint2*)&Kt[0][lrow * KSTRIDE + lseg] = *(const uint2*)&Kg[lrow * 16 + lseg];
    *(uint2*)&Vt[0][lrow * KSTRIDE + lseg] = *(const uint2*)&Vg[lrow * 16 + lseg];
    __syncthreads();

    // hoist the constant ones-column B-fragment (identical for every tile/kc)
    uint32_t on0, on1;
    {
        uint32_t a = (uint32_t)__cvta_generic_to_shared(
            &Vt[0][(lane & 15) * KSTRIDE + 16]);
        asm volatile("ldmatrix.sync.aligned.m8n8.x2.trans.shared.b16 {%0,%1}, [%2];"
                     : "=r"(on0), "=r"(on1) : "r"(a));
    }

    int buf = 0;
    for (int kt = 0; kt < NN / 64; kt++) {
        uint2 kp, vp;
        const bool more = (kt + 1 < NN / 64);
        if (more) {
            kp = *(const uint2*)&Kg[((kt + 1) * 64 + lrow) * 16 + lseg];
            vp = *(const uint2*)&Vg[((kt + 1) * 64 + lrow) * 16 + lseg];
        }

        // ---- S = Q@K^T with f16 accumulators: output feeds ex2 directly (no cvt packs) ----
        uint32_t ps[8][2];
#pragma unroll
        for (int p = 0; p < 4; p++) {
            uint32_t kb[4];
            uint32_t a = (uint32_t)__cvta_generic_to_shared(
                &Kt[buf][((2 * p + (lane >> 4)) * 8 + (lane & 7)) * KSTRIDE +
                         ((lane >> 3) & 1) * 8]);
            asm volatile("ldmatrix.sync.aligned.m8n8.x4.shared.b16 {%0,%1,%2,%3}, [%4];"
                         : "=r"(kb[0]), "=r"(kb[1]), "=r"(kb[2]), "=r"(kb[3]) : "r"(a));
#pragma unroll
            for (int u = 0; u < 2; u++) {
                uint32_t d0, d1;
                asm volatile("mma.sync.aligned.m16n8k16.row.col.f16.f16.f16.f16 "
                             "{%0,%1}, {%2,%3,%4,%5}, {%6,%7}, {%8,%9};"
                             : "=r"(d0), "=r"(d1)
                             : "r"(qa[0]), "r"(qa[1]), "r"(qa[2]), "r"(qa[3]),
                               "r"(kb[2 * u]), "r"(kb[2 * u + 1]),
                               "r"(0u), "r"(0u));
                ps[2 * p + u][0] = ex2h2(d0);
                ps[2 * p + u][1] = ex2h2(d1);
            }
        }
        // ---- O += P @ [V | ones] ----
#pragma unroll
        for (int kc = 0; kc < 4; kc++) {
            uint32_t vb[4];
            uint32_t a = (uint32_t)__cvta_generic_to_shared(
                &Vt[buf][(kc * 16 + (lane & 15)) * KSTRIDE + ((lane >> 4) & 1) * 8]);
            asm volatile("ldmatrix.sync.aligned.m8n8.x4.trans.shared.b16 {%0,%1,%2,%3}, [%4];"
                         : "=r"(vb[0]), "=r"(vb[1]), "=r"(vb[2]), "=r"(vb[3]) : "r"(a));
#pragma unroll
            for (int dt = 0; dt < 2; dt++)
                asm volatile("mma.sync.aligned.m16n8k16.row.col.f32.f16.f16.f32 "
                             "{%0,%1,%2,%3}, {%4,%5,%6,%7}, {%8,%9}, {%0,%1,%2,%3};"
                             : "+f"(o[dt][0]), "+f"(o[dt][1]), "+f"(o[dt][2]), "+f"(o[dt][3])
                             : "r"(ps[2 * kc][0]), "r"(ps[2 * kc][1]),
                               "r"(ps[2 * kc + 1][0]), "r"(ps[2 * kc + 1][1]),
                               "r"(vb[2 * dt]), "r"(vb[2 * dt + 1]));
            asm volatile("mma.sync.aligned.m16n8k16.row.col.f32.f16.f16.f32 "
                         "{%0,%1,%2,%3}, {%4,%5,%6,%7}, {%8,%9}, {%0,%1,%2,%3};"
                         : "+f"(o[2][0]), "+f"(o[2][1]), "+f"(o[2][2]), "+f"(o[2][3])
                         : "r"(ps[2 * kc][0]), "r"(ps[2 * kc][1]),
                           "r"(ps[2 * kc + 1][0]), "r"(ps[2 * kc + 1][1]),
                           "r"(on0), "r"(on1));
        }

        if (more) {
            *(uint2*)&Kt[buf ^ 1][lrow * KSTRIDE + lseg] = kp;
            *(uint2*)&Vt[buf ^ 1][lrow * KSTRIDE + lseg] = vp;
        }
        __syncthreads();
        buf ^= 1;
    }

    // row sums live in the ones-column of the third accumulator, held by c==0 lanes
    const float l0 = __shfl_sync(0xffffffff, o[2][0], lane & ~3);
    const float l1 = __shfl_sync(0xffffffff, o[2][2], lane & ~3);
    const float i0 = 1.f / l0, i1 = 1.f / l1;

    const int qrow = q0 + w * 16 + g;
    const int cb   = 256 + h * 16 + 2 * c;
    *(__half2*)&hcatH[(size_t)qrow * 320 + cb] =
        __floats2half2_rn(o[0][0] * i0, o[0][1] * i0);
    *(__half2*)&hcatH[(size_t)qrow * 320 + cb + 8] =
        __floats2half2_rn(o[1][0] * i0, o[1][1] * i0);
    *(__half2*)&hcatH[(size_t)(qrow + 8) * 320 + cb] =
        __floats2half2_rn(o[0][2] * i1, o[0][3] * i1);
    *(__half2*)&hcatH[(size_t)(qrow + 8) * 320 + cb + 8] =
        __floats2half2_rn(o[1][2] * i1, o[1][3] * i1);
}

// ---------------- CSR scan (deg counted by prep; +1 self loop; reset deg) ----------------
__global__ void __launch_bounds__(1024) k_scan()
{
    __shared__ int wsum[32];
    const int tid = threadIdx.x, lane = tid & 31, wid = tid >> 5;
    const int base = tid * 8;
    int v[8], s = 0;
#pragma unroll
    for (int j = 0; j < 8; j++) {
        v[j] = g_deg[base + j] + 1;
        g_deg[base + j] = 0;
        s += v[j];
    }
    int inc = s;
#pragma unroll
    for (int off = 1; off < 32; off <<= 1) {
        int u = __shfl_up_sync(0xffffffff, inc, off);
        if (lane >= off) inc += u;
    }
    if (lane == 31) wsum[wid] = inc;
    __syncthreads();
    if (wid == 0) {
        int t = wsum[lane];
#pragma unroll
        for (int off = 1; off < 32; off <<= 1) {
            int p = __shfl_up_sync(0xffffffff, t, off);
            if (lane >= off) t += p;
        }
        wsum[lane] = t;
    }
    __syncthreads();
    int run = inc - s + (wid ? wsum[wid - 1] : 0);
#pragma unroll
    for (int j = 0; j < 8; j++) {
        int node = base + j;
        g_rowptr[node] = run;
        g_cursor[node] = run;
        g_dinv[node] = rsqrtf((float)v[j]);
        run += v[j];
    }
    if (tid == 1023) g_rowptr[NN] = run;
}

__global__ void __launch_bounds__(256) k_fill(const int* __restrict__ ei)
{
    int e4 = (blockIdx.x * 256 + threadIdx.x) * 4;
    if (e4 < NEDGE) {
        int4 s = *(const int4*)&ei[e4];
        int4 d = *(const int4*)&ei[NEDGE + e4];
        int p0 = atomicAdd(&g_cursor[d.x], 1);
        int p1 = atomicAdd(&g_cursor[d.y], 1);
        int p2 = atomicAdd(&g_cursor[d.z], 1);
        int p3 = atomicAdd(&g_cursor[d.w], 1);
        g_col[p0] = s.x; g_col[p1] = s.y; g_col[p2] = s.z; g_col[p3] = s.w;
    } else {
        int n = e4 - NEDGE;
#pragma unroll
        for (int j = 0; j < 4; j++) {
            int pos = atomicAdd(&g_cursor[n + j], 1);
            g_col[pos] = n + j;
        }
    }
}

// ---------------- GCN aggregation: out = relu(di*(a + cvec*ws) + b), f16 out ----------------
template<bool RELU>
__global__ void __launch_bounds__(256) agg256(const __half* __restrict__ hw,
                                              const float* __restrict__ bias,
                                              const float* __restrict__ cvec,
                                              __half* __restrict__ outH)
{
    int gwarp = (blockIdx.x * blockDim.x + threadIdx.x) >> 5;
    int node = gwarp >> 1;
    const int lane = threadIdx.x & 31;
    const int c = (gwarp & 1) * 128 + lane * 4;
    const int r0 = g_rowptr[node], r1 = g_rowptr[node + 1];
    const float di = g_dinv[node];

    float a[4] = {0.f, 0.f, 0.f, 0.f};
    float ws = 0.f;
    int sc = g_col[r0];
    for (int e = r0; e < r1; e++) {
        int s = sc;
        if (e + 1 < r1) sc = g_col[e + 1];
        float w = g_dinv[s];
        ws += w;
        uint2 raw = *(const uint2*)&hw[(size_t)s * 256 + c];
        float2 f01 = __half22float2(*(__half2*)&raw.x);
        float2 f23 = __half22float2(*(__half2*)&raw.y);
        a[0] = fmaf(w, f01.x, a[0]); a[1] = fmaf(w, f01.y, a[1]);
        a[2] = fmaf(w, f23.x, a[2]); a[3] = fmaf(w, f23.y, a[3]);
    }
    float o[4];
#pragma unroll
    for (int j = 0; j < 4; j++) {
        o[j] = fmaf(di, fmaf(cvec[c + j], ws, a[j]), bias[c + j]);
        if (RELU) o[j] = fmaxf(o[j], 0.f);
    }
    uint2 st;
    *(__half2*)&st.x = __floats2half2_rn(o[0], o[1]);
    *(__half2*)&st.y = __floats2half2_rn(o[2], o[3]);
    *(uint2*)&outH[(size_t)node * 256 + c] = st;
}

// F=64 final layer, fp32 out
__global__ void __launch_bounds__(256) agg64(const __half* __restrict__ hw,
                                             const float* __restrict__ bias,
                                             float* __restrict__ out)
{
    int node = (blockIdx.x * blockDim.x + threadIdx.x) >> 5;
    const int lane = threadIdx.x & 31;
    const int c = lane * 2;
    const int r0 = g_rowptr[node], r1 = g_rowptr[node + 1];
    const float di = g_dinv[node];

    float ax = 0.f, ay = 0.f;
    int sc = g_col[r0];
    for (int e = r0; e < r1; e++) {
        int s = sc;
        if (e + 1 < r1) sc = g_col[e + 1];
        float w = g_dinv[s];
        float2 f = __half22float2(*(const __half2*)&hw[(size_t)s * 64 + c]);
        ax = fmaf(w, f.x, ax);
        ay = fmaf(w, f.y, ay);
    }
    float2 o;
    o.x = fmaf(di, ax, bias[c]);
    o.y = fmaf(di, ay, bias[c + 1]);
    *(float2*)&out[(size_t)node * 64 + c] = o;
}

// ---------------- launch ----------------
extern "C" void kernel_launch(void* const* d_in, const int* in_sizes, int n_in,
                              void* d_out, int out_size)
{
    const float* x    = (const float*)d_in[0];
    const int*   ei   = (const int*)d_in[1];
    const float* pe_w = (const float*)d_in[2];
    const float* pe_b = (const float*)d_in[3];
    const float* ipw  = (const float*)d_in[4];
    const float* ipb  = (const float*)d_in[5];
    const float* opw  = (const float*)d_in[6];
    const float* opb  = (const float*)d_in[7];
    const float* w1   = (const float*)d_in[8];
    const float* b1   = (const float*)d_in[9];
    const float* w2   = (const float*)d_in[10];
    const float* b2   = (const float*)d_in[11];
    const float* w3   = (const float*)d_in[12];
    const float* b3   = (const float*)d_in[13];
    float* out = (float*)d_out;

    __half *hcatH, *t2H, *Bc, *Bw1, *Bw2, *Bw3, *t1h, *Qh, *Kh, *Vh;
    float *bc, *cvec, *zero;
    cudaGetSymbolAddress((void**)&hcatH, g_hcatH);
    cudaGetSymbolAddress((void**)&t2H,   g_t2H);
    cudaGetSymbolAddress((void**)&Bc,    g_Bc);
    cudaGetSymbolAddress((void**)&Bw1,   g_Bw1);
    cudaGetSymbolAddress((void**)&Bw2,   g_Bw2);
    cudaGetSymbolAddress((void**)&Bw3,   g_Bw3);
    cudaGetSymbolAddress((void**)&Qh,    g_Qh);
    cudaGetSymbolAddress((void**)&Kh,    g_Kh);
    cudaGetSymbolAddress((void**)&Vh,    g_Vh);
    cudaGetSymbolAddress((void**)&t1h,   g_t1h);
    cudaGetSymbolAddress((void**)&bc,    g_bc);
    cudaGetSymbolAddress((void**)&cvec,  g_cvec);
    cudaGetSymbolAddress((void**)&zero,  g_zero);

    prep<<<3138, 256>>>(x, w1, w2, w3, pe_w, ipw, opw, opb, pe_b, ipb, ei);
    k_scan<<<1, 1024>>>();
    k_fill<<<TE / 1024, 256>>>(ei);

    // qkv = x @ Wc + bc -> Q/K/V (f16); reads hcat x-cols (K=256, lda=320)
    gemm_mma<128, 2><<<dim3(NN / 128, 3), 256>>>(hcatH, Bc, bc, nullptr,
                                                 256, 320, 0, Qh, Kh, Vh);
    attn_mma<<<dim3(NN / QTILE, NH), 256>>>(Qh, Kh, Vh, hcatH);

    // GCN stack (out_proj folded into w1; +opb via cvec pre-aggregation)
    gemm_mma<128, 0><<<dim3(NN / 128, 4), 256>>>(hcatH, Bw1, nullptr, t1h,
                                                 320, 320, 256, nullptr, nullptr, nullptr);
    agg256<true><<<NN * 64 / 256, 256>>>(t1h, b1, cvec, t2H);
    gemm_mma<128, 0><<<dim3(NN / 128, 4), 256>>>(t2H, Bw2, nullptr, t1h,
                                                 256, 256, 256, nullptr, nullptr, nullptr);
    agg256<true><<<NN * 64 / 256, 256>>>(t1h, b2, zero, t2H);
    gemm_mma<64, 0><<<dim3(NN / 64, 1), 256>>>(t2H, Bw3, nullptr, t1h,
                                               256, 256, 64, nullptr, nullptr, nullptr);
    agg64<<<NN * 32 / 256, 256>>>(t1h, b3, out);
}

// round 13
// speedup vs baseline: 1.0554x; 1.0043x over previous
#include <cuda_runtime.h>
#include <cuda_fp16.h>
#include <cstdint>

#define NN    8192
#define NH    4
#define DH    16
#define NEDGE 262144
#define TE    (NEDGE + NN)

// ---------------- scratch ----------------
__device__ __half g_hcatH[NN * 320];    // [x(256) | attn(64)] f16 single copy
__device__ __half g_t2H[NN * 256];      // t2 f16
__device__ __half g_Bc[192 * 256];      // combined qkv weights, plain f16
__device__ __half g_Bw1[256 * 320];     // folded w1, plain f16
__device__ __half g_Bw2[256 * 256];
__device__ __half g_Bw3[64 * 256];
__device__ float g_bc[192];             // combined qkv bias
__device__ float g_cvec[256];           // opb @ w1_bot (pre-aggregation constant)
__device__ float g_zero[256];           // stays 0
__device__ __half g_t1h[NN * 256];
__device__ int   g_deg[NN];             // zero at entry; k_scan re-zeroes for replay
__device__ int   g_rowptr[NN + 1];
__device__ int   g_cursor[NN];
__device__ int   g_col[TE];
__device__ float g_dinv[NN];
__device__ __half g_Qh[NH * NN * DH];
__device__ __half g_Kh[NH * NN * DH];
__device__ __half g_Vh[NH * NN * DH];

__device__ __forceinline__ uint32_t ex2h2(uint32_t h) {
    uint32_t r;
    asm("ex2.approx.f16x2 %0, %1;" : "=r"(r) : "r"(h));
    return r;
}

// ---------------- mega prep ----------------
// blocks: [0,2048) x | [2048,2304) w1 | [2304,2560) w2 | [2560,2624) w3
//         [2624,2816) Wc | [2816,2880) Wb | [2880,2882) biases | [2882,3138) edge count
__global__ void __launch_bounds__(256) prep(const float* __restrict__ x,
                                            const float* __restrict__ w1,
                                            const float* __restrict__ w2,
                                            const float* __restrict__ w3,
                                            const float* __restrict__ pe_w,
                                            const float* __restrict__ ipw,
                                            const float* __restrict__ opw,
                                            const float* __restrict__ opb,
                                            const float* __restrict__ pe_b,
                                            const float* __restrict__ ipb,
                                            const int* __restrict__ ei)
{
    const int b = blockIdx.x, t = threadIdx.x;
    if (b < 2048) {
        int idx = b * 256 + t;                 // NN*64
        int m = idx >> 6, kk = (idx & 63) * 4;
        float4 v = *(const float4*)&x[(size_t)m * 256 + kk];
        __half2 h0 = __floats2half2_rn(v.x, v.y);
        __half2 h1 = __floats2half2_rn(v.z, v.w);
        __half2* dst = (__half2*)&g_hcatH[(size_t)m * 320 + kk];
        dst[0] = h0; dst[1] = h1;
    } else if (b < 2304) {
        int idx = (b - 2048) * 256 + t;
        int k = idx >> 8, n = idx & 255;
        g_Bw1[n * 320 + k] = __float2half(w1[k * 256 + n]);
    } else if (b < 2560) {
        int idx = (b - 2304) * 256 + t;
        int k = idx >> 8, n = idx & 255;
        g_Bw2[n * 256 + k] = __float2half(w2[k * 256 + n]);
    } else if (b < 2624) {
        int idx = (b - 2560) * 256 + t;
        int k = idx >> 6, n = idx & 63;
        g_Bw3[n * 256 + k] = __float2half(w3[k * 64 + n]);
    } else if (b < 2816) {                     // Wc = pe_w @ ipw^T
        int idx = (b - 2624) * 256 + t;
        int n = idx >> 8, k = idx & 255;
        float s = 0.f;
#pragma unroll 8
        for (int d = 0; d < 64; d++)
            s = fmaf(ipw[n * 64 + d], pe_w[k * 64 + d], s);
        g_Bc[n * 256 + k] = __float2half(s);
    } else if (b < 2880) {                     // Wb = opw^T @ w1_bot
        int idx = (b - 2816) * 256 + t;
        int d = idx >> 8, n = idx & 255;
        float s = 0.f;
#pragma unroll 8
        for (int j = 0; j < 64; j++)
            s = fmaf(opw[j * 64 + d], w1[(256 + j) * 256 + n], s);
        g_Bw1[n * 320 + 256 + d] = __float2half(s);
    } else if (b < 2882) {
        int i = (b - 2880) * 256 + t;
        if (i < 256) {                         // cvec = opb @ w1_bot
            float s = 0.f;
#pragma unroll 8
            for (int j = 0; j < 64; j++)
                s = fmaf(opb[j], w1[(256 + j) * 256 + i], s);
            g_cvec[i] = s;
        } else if (i < 448) {                  // bc = pe_b @ ipw^T + ipb
            int n = i - 256;
            float s = ipb[n];
#pragma unroll 8
            for (int d = 0; d < 64; d++)
                s = fmaf(ipw[n * 64 + d], pe_b[d], s);
            g_bc[n] = s;
        }
    } else {                                   // edge degree count, 4 edges/thread
        int e4 = ((b - 2882) * 256 + t) * 4;
        int4 d = *(const int4*)&ei[NEDGE + e4];
        atomicAdd(&g_deg[d.x], 1);
        atomicAdd(&g_deg[d.y], 1);
        atomicAdd(&g_deg[d.z], 1);
        atomicAdd(&g_deg[d.w], 1);
    }
}

// ---------------- plain f16 tensor-core GEMM ----------------
// C[M,N] = A[M,K] @ B[N,K]^T.
// EPI: 0 = f16 C (+bias), 2 = QKV f16 (+bias, Q scaled)
template<int BM, int EPI>
__global__ void __launch_bounds__(256) gemm_mma(
    const __half* __restrict__ A, const __half* __restrict__ B,
    const float* __restrict__ bias, void* __restrict__ outp,
    int K, int lda, int ldc,
    __half* __restrict__ Qh, __half* __restrict__ Kh, __half* __restrict__ Vh)
{
    constexpr int NWN  = (BM == 128) ? 2 : 4;
    constexpr int WN   = 64 / NWN;
    constexpr int NT   = WN / 8;
    constexpr int AREP = BM / 64;

    __shared__ __half As[2][BM * 40];
    __shared__ __half Bs[2][64 * 40];

    const int t = threadIdx.x, warp = t >> 5, lane = t & 31;
    const int wm = warp / NWN, wn = warp % NWN;
    const int bm = blockIdx.x * BM, bn = blockIdx.y * 64;

    float acc[2][NT][4];
#pragma unroll
    for (int i = 0; i < 2; i++)
#pragma unroll
        for (int j = 0; j < NT; j++)
#pragma unroll
            for (int q = 0; q < 4; q++) acc[i][j][q] = 0.f;

    const int brow = t >> 2, bcg = t & 3;
#pragma unroll
    for (int i = 0; i < AREP; i++) {
        int idx = t + i * 256, row = idx >> 2, cg = idx & 3;
        *(uint4*)&As[0][row * 40 + cg * 8] =
            *(const uint4*)&A[(size_t)(bm + row) * lda + cg * 8];
    }
    *(uint4*)&Bs[0][brow * 40 + bcg * 8] =
        *(const uint4*)&B[(size_t)(bn + brow) * K + bcg * 8];
    __syncthreads();

    const int nk = K >> 5;
    int buf = 0;
    for (int kc = 0; kc < nk; kc++) {
        uint4 pa[AREP], pb;
        const bool more = (kc + 1 < nk);
        if (more) {
            int k0 = (kc + 1) << 5;
#pragma unroll
            for (int i = 0; i < AREP; i++) {
                int idx = t + i * 256, row = idx >> 2, cg = idx & 3;
                pa[i] = *(const uint4*)&A[(size_t)(bm + row) * lda + k0 + cg * 8];
            }
            pb = *(const uint4*)&B[(size_t)(bn + brow) * K + k0 + bcg * 8];
        }

#pragma unroll
        for (int kk = 0; kk < 2; kk++) {
            uint32_t af[2][4];
#pragma unroll
            for (int mt = 0; mt < 2; mt++) {
                uint32_t a = (uint32_t)__cvta_generic_to_shared(
                    &As[buf][(wm * 32 + mt * 16 + (lane & 15)) * 40 + kk * 16 + (lane >> 4) * 8]);
                asm volatile("ldmatrix.sync.aligned.m8n8.x4.shared.b16 {%0,%1,%2,%3}, [%4];"
                             : "=r"(af[mt][0]), "=r"(af[mt][1]), "=r"(af[mt][2]), "=r"(af[mt][3])
                             : "r"(a));
            }
            uint32_t bfg[NT][2];
#pragma unroll
            for (int p = 0; p < NT / 2; p++) {
                uint32_t a = (uint32_t)__cvta_generic_to_shared(
                    &Bs[buf][(wn * WN + (2 * p + (lane >> 4)) * 8 + (lane & 7)) * 40 +
                             kk * 16 + ((lane >> 3) & 1) * 8]);
                asm volatile("ldmatrix.sync.aligned.m8n8.x4.shared.b16 {%0,%1,%2,%3}, [%4];"
                             : "=r"(bfg[2 * p][0]), "=r"(bfg[2 * p][1]),
                               "=r"(bfg[2 * p + 1][0]), "=r"(bfg[2 * p + 1][1])
                             : "r"(a));
            }
#pragma unroll
            for (int mt = 0; mt < 2; mt++)
#pragma unroll
                for (int nt = 0; nt < NT; nt++)
                    asm volatile("mma.sync.aligned.m16n8k16.row.col.f32.f16.f16.f32 "
                                 "{%0,%1,%2,%3}, {%4,%5,%6,%7}, {%8,%9}, {%0,%1,%2,%3};"
                                 : "+f"(acc[mt][nt][0]), "+f"(acc[mt][nt][1]),
                                   "+f"(acc[mt][nt][2]), "+f"(acc[mt][nt][3])
                                 : "r"(af[mt][0]), "r"(af[mt][1]), "r"(af[mt][2]), "r"(af[mt][3]),
                                   "r"(bfg[nt][0]), "r"(bfg[nt][1]));
        }

        if (more) {
#pragma unroll
            for (int i = 0; i < AREP; i++) {
                int idx = t + i * 256, row = idx >> 2, cg = idx & 3;
                *(uint4*)&As[buf ^ 1][row * 40 + cg * 8] = pa[i];
            }
            *(uint4*)&Bs[buf ^ 1][brow * 40 + bcg * 8] = pb;
        }
        __syncthreads();
        buf ^= 1;
    }

#pragma unroll
    for (int nt = 0; nt < NT; nt++) {
        const int col0 = bn + wn * WN + nt * 8 + (lane & 3) * 2;
        float2 bv = make_float2(0.f, 0.f);
        if (bias) bv = *(const float2*)&bias[col0];
#pragma unroll
        for (int mt = 0; mt < 2; mt++) {
            const int r0 = bm + wm * 32 + mt * 16 + (lane >> 2);
            float v00 = acc[mt][nt][0] + bv.x, v01 = acc[mt][nt][1] + bv.y;
            float v10 = acc[mt][nt][2] + bv.x, v11 = acc[mt][nt][3] + bv.y;
            if (EPI == 0) {
                __half* C = (__half*)outp;
                *(__half2*)&C[(size_t)r0 * ldc + col0]       = __floats2half2_rn(v00, v01);
                *(__half2*)&C[(size_t)(r0 + 8) * ldc + col0] = __floats2half2_rn(v10, v11);
            } else {
                int sec = col0 >> 6;
                int h   = (col0 & 63) >> 4;
                int d   = col0 & 15;
                if (sec == 0) {
                    v00 *= 0.36067376022224085f; v01 *= 0.36067376022224085f;
                    v10 *= 0.36067376022224085f; v11 *= 0.36067376022224085f;
                }
                __half* dst = (sec == 0) ? Qh : (sec == 1 ? Kh : Vh);
                *(__half2*)&dst[(((size_t)h * NN + r0) << 4) + d] =
                    __floats2half2_rn(v00, v01);
                *(__half2*)&dst[(((size_t)h * NN + r0 + 8) << 4) + d] =
                    __floats2half2_rn(v10, v11);
            }
        }
    }
}

// ---------------- tensor-core flash attention: f16 QK accum, KTILE=64 ----------------
#define KSTRIDE 24
#define QTILE 128

__global__ void __launch_bounds__(256) attn_mma(const __half* __restrict__ Qh,
                                                const __half* __restrict__ Kh,
                                                const __half* __restrict__ Vh,
                                                __half* __restrict__ hcatH)
{
    __shared__ __half Kt[2][64 * KSTRIDE];
    __shared__ __half Vt[2][64 * KSTRIDE];
    const int tid  = threadIdx.x;
    const int w    = tid >> 5, lane = tid & 31;
    const int h    = blockIdx.y;
    const int q0   = blockIdx.x * QTILE;
    const int g    = lane >> 2, c = lane & 3;

    uint32_t qa[4];
    {
        const __half* qb = Qh + (((size_t)h * NN + q0 + w * 16) << 4);
        qa[0] = *(const uint32_t*)&qb[(g)     * 16 + 2 * c];
        qa[1] = *(const uint32_t*)&qb[(g + 8) * 16 + 2 * c];
        qa[2] = *(const uint32_t*)&qb[(g)     * 16 + 2 * c + 8];
        qa[3] = *(const uint32_t*)&qb[(g + 8) * 16 + 2 * c + 8];
    }

    float o[3][4];
#pragma unroll
    for (int i = 0; i < 3; i++)
#pragma unroll
        for (int j = 0; j < 4; j++) o[i][j] = 0.f;

    const int lrow = tid >> 2;
    const int lseg = (tid & 3) * 4;
    const __half* Kg = Kh + ((size_t)h * NN << 4);
    const __half* Vg = Vh + ((size_t)h * NN << 4);

    // ones-column constants at Vt cols [16..23]: col16 = 1.0h, rest 0. Never overwritten
    // (mainloop writes cols [0,16) only).
#pragma unroll
    for (int j = 0; j < 2; j++) {
        int idx = tid * 2 + j;
        int bu = idx >> 8, row = (idx >> 2) & 63, pr = idx & 3;
        *(uint32_t*)&Vt[bu][row * KSTRIDE + 16 + pr * 2] = (pr == 0) ? 0x00003C00u : 0u;
    }

    *(uint2*)&Kt[0][lrow * KSTRIDE + lseg] = *(const uint2*)&Kg[lrow * 16 + lseg];
    *(uint2*)&Vt[0][lrow * KSTRIDE + lseg] = *(const uint2*)&Vg[lrow * 16 + lseg];
    __syncthreads();

    // hoist the constant ones-column B-fragment (identical for every tile/kc)
    uint32_t on0, on1;
    {
        uint32_t a = (uint32_t)__cvta_generic_to_shared(
            &Vt[0][(lane & 15) * KSTRIDE + 16]);
        asm volatile("ldmatrix.sync.aligned.m8n8.x2.trans.shared.b16 {%0,%1}, [%2];"
                     : "=r"(on0), "=r"(on1) : "r"(a));
    }

    int buf = 0;
    for (int kt = 0; kt < NN / 64; kt++) {
        uint2 kp, vp;
        const bool more = (kt + 1 < NN / 64);
        if (more) {
            kp = *(const uint2*)&Kg[((kt + 1) * 64 + lrow) * 16 + lseg];
            vp = *(const uint2*)&Vg[((kt + 1) * 64 + lrow) * 16 + lseg];
        }

        // ---- S = Q@K^T with f16 accumulators: output feeds ex2 directly (no cvt packs) ----
        uint32_t ps[8][2];
#pragma unroll
        for (int p = 0; p < 4; p++) {
            uint32_t kb[4];
            uint32_t a = (uint32_t)__cvta_generic_to_shared(
                &Kt[buf][((2 * p + (lane >> 4)) * 8 + (lane & 7)) * KSTRIDE +
                         ((lane >> 3) & 1) * 8]);
            asm volatile("ldmatrix.sync.aligned.m8n8.x4.shared.b16 {%0,%1,%2,%3}, [%4];"
                         : "=r"(kb[0]), "=r"(kb[1]), "=r"(kb[2]), "=r"(kb[3]) : "r"(a));
#pragma unroll
            for (int u = 0; u < 2; u++) {
                uint32_t d0, d1;
                asm volatile("mma.sync.aligned.m16n8k16.row.col.f16.f16.f16.f16 "
                             "{%0,%1}, {%2,%3,%4,%5}, {%6,%7}, {%8,%9};"
                             : "=r"(d0), "=r"(d1)
                             : "r"(qa[0]), "r"(qa[1]), "r"(qa[2]), "r"(qa[3]),
                               "r"(kb[2 * u]), "r"(kb[2 * u + 1]),
                               "r"(0u), "r"(0u));
                ps[2 * p + u][0] = ex2h2(d0);
                ps[2 * p + u][1] = ex2h2(d1);
            }
        }
        // ---- O += P @ [V | ones] ----
#pragma unroll
        for (int kc = 0; kc < 4; kc++) {
            uint32_t vb[4];
            uint32_t a = (uint32_t)__cvta_generic_to_shared(
                &Vt[buf][(kc * 16 + (lane & 15)) * KSTRIDE + ((lane >> 4) & 1) * 8]);
            asm volatile("ldmatrix.sync.aligned.m8n8.x4.trans.shared.b16 {%0,%1,%2,%3}, [%4];"
                         : "=r"(vb[0]), "=r"(vb[1]), "=r"(vb[2]), "=r"(vb[3]) : "r"(a));
#pragma unroll
            for (int dt = 0; dt < 2; dt++)
                asm volatile("mma.sync.aligned.m16n8k16.row.col.f32.f16.f16.f32 "
                             "{%0,%1,%2,%3}, {%4,%5,%6,%7}, {%8,%9}, {%0,%1,%2,%3};"
                             : "+f"(o[dt][0]), "+f"(o[dt][1]), "+f"(o[dt][2]), "+f"(o[dt][3])
                             : "r"(ps[2 * kc][0]), "r"(ps[2 * kc][1]),
                               "r"(ps[2 * kc + 1][0]), "r"(ps[2 * kc + 1][1]),
                               "r"(vb[2 * dt]), "r"(vb[2 * dt + 1]));
            asm volatile("mma.sync.aligned.m16n8k16.row.col.f32.f16.f16.f32 "
                         "{%0,%1,%2,%3}, {%4,%5,%6,%7}, {%8,%9}, {%0,%1,%2,%3};"
                         : "+f"(o[2][0]), "+f"(o[2][1]), "+f"(o[2][2]), "+f"(o[2][3])
                         : "r"(ps[2 * kc][0]), "r"(ps[2 * kc][1]),
                           "r"(ps[2 * kc + 1][0]), "r"(ps[2 * kc + 1][1]),
                           "r"(on0), "r"(on1));
        }

        if (more) {
            *(uint2*)&Kt[buf ^ 1][lrow * KSTRIDE + lseg] = kp;
            *(uint2*)&Vt[buf ^ 1][lrow * KSTRIDE + lseg] = vp;
        }
        __syncthreads();
        buf ^= 1;
    }

    // row sums live in the ones-column of the third accumulator, held by c==0 lanes
    const float l0 = __shfl_sync(0xffffffff, o[2][0], lane & ~3);
    const float l1 = __shfl_sync(0xffffffff, o[2][2], lane & ~3);
    const float i0 = 1.f / l0, i1 = 1.f / l1;

    const int qrow = q0 + w * 16 + g;
    const int cb   = 256 + h * 16 + 2 * c;
    *(__half2*)&hcatH[(size_t)qrow * 320 + cb] =
        __floats2half2_rn(o[0][0] * i0, o[0][1] * i0);
    *(__half2*)&hcatH[(size_t)qrow * 320 + cb + 8] =
        __floats2half2_rn(o[1][0] * i0, o[1][1] * i0);
    *(__half2*)&hcatH[(size_t)(qrow + 8) * 320 + cb] =
        __floats2half2_rn(o[0][2] * i1, o[0][3] * i1);
    *(__half2*)&hcatH[(size_t)(qrow + 8) * 320 + cb + 8] =
        __floats2half2_rn(o[1][2] * i1, o[1][3] * i1);
}

// ---------------- CSR scan (deg counted by prep; +1 self loop; reset deg) ----------------
__global__ void __launch_bounds__(1024) k_scan()
{
    __shared__ int wsum[32];
    const int tid = threadIdx.x, lane = tid & 31, wid = tid >> 5;
    const int base = tid * 8;
    int v[8], s = 0;
#pragma unroll
    for (int j = 0; j < 8; j++) {
        v[j] = g_deg[base + j] + 1;
        g_deg[base + j] = 0;
        s += v[j];
    }
    int inc = s;
#pragma unroll
    for (int off = 1; off < 32; off <<= 1) {
        int u = __shfl_up_sync(0xffffffff, inc, off);
        if (lane >= off) inc += u;
    }
    if (lane == 31) wsum[wid] = inc;
    __syncthreads();
    if (wid == 0) {
        int t = wsum[lane];
#pragma unroll
        for (int off = 1; off < 32; off <<= 1) {
            int p = __shfl_up_sync(0xffffffff, t, off);
            if (lane >= off) t += p;
        }
        wsum[lane] = t;
    }
    __syncthreads();
    int run = inc - s + (wid ? wsum[wid - 1] : 0);
#pragma unroll
    for (int j = 0; j < 8; j++) {
        int node = base + j;
        g_rowptr[node] = run;
        g_cursor[node] = run;
        g_dinv[node] = rsqrtf((float)v[j]);
        run += v[j];
    }
    if (tid == 1023) g_rowptr[NN] = run;
}

// 8 edges/thread for atomic ILP. First 128 blocks cover NEDGE, last 4 the self loops.
__global__ void __launch_bounds__(256) k_fill(const int* __restrict__ ei)
{
    int e8 = (blockIdx.x * 256 + threadIdx.x) * 8;
    if (e8 < NEDGE) {
        int4 s0 = *(const int4*)&ei[e8];
        int4 s1 = *(const int4*)&ei[e8 + 4];
        int4 d0 = *(const int4*)&ei[NEDGE + e8];
        int4 d1 = *(const int4*)&ei[NEDGE + e8 + 4];
        int p0 = atomicAdd(&g_cursor[d0.x], 1);
        int p1 = atomicAdd(&g_cursor[d0.y], 1);
        int p2 = atomicAdd(&g_cursor[d0.z], 1);
        int p3 = atomicAdd(&g_cursor[d0.w], 1);
        int p4 = atomicAdd(&g_cursor[d1.x], 1);
        int p5 = atomicAdd(&g_cursor[d1.y], 1);
        int p6 = atomicAdd(&g_cursor[d1.z], 1);
        int p7 = atomicAdd(&g_cursor[d1.w], 1);
        g_col[p0] = s0.x; g_col[p1] = s0.y; g_col[p2] = s0.z; g_col[p3] = s0.w;
        g_col[p4] = s1.x; g_col[p5] = s1.y; g_col[p6] = s1.z; g_col[p7] = s1.w;
    } else {
        int n = e8 - NEDGE;
#pragma unroll
        for (int j = 0; j < 8; j++) {
            int pos = atomicAdd(&g_cursor[n + j], 1);
            g_col[pos] = n + j;
        }
    }
}

// ---------------- GCN aggregation: out = relu(di*(a + cvec*ws) + b), f16 out ----------------
template<bool RELU>
__global__ void __launch_bounds__(256) agg256(const __half* __restrict__ hw,
                                              const float* __restrict__ bias,
                                              const float* __restrict__ cvec,
                                              __half* __restrict__ outH)
{
    int gwarp = (blockIdx.x * blockDim.x + threadIdx.x) >> 5;
    int node = gwarp >> 1;
    const int lane = threadIdx.x & 31;
    const int c = (gwarp & 1) * 128 + lane * 4;
    const int r0 = g_rowptr[node], r1 = g_rowptr[node + 1];
    const float di = g_dinv[node];

    float a[4] = {0.f, 0.f, 0.f, 0.f};
    float ws = 0.f;
    int sc = g_col[r0];
    for (int e = r0; e < r1; e++) {
        int s = sc;
        if (e + 1 < r1) sc = g_col[e + 1];
        float w = g_dinv[s];
        ws += w;
        uint2 raw = *(const uint2*)&hw[(size_t)s * 256 + c];
        float2 f01 = __half22float2(*(__half2*)&raw.x);
        float2 f23 = __half22float2(*(__half2*)&raw.y);
        a[0] = fmaf(w, f01.x, a[0]); a[1] = fmaf(w, f01.y, a[1]);
        a[2] = fmaf(w, f23.x, a[2]); a[3] = fmaf(w, f23.y, a[3]);
    }
    float o[4];
#pragma unroll
    for (int j = 0; j < 4; j++) {
        o[j] = fmaf(di, fmaf(cvec[c + j], ws, a[j]), bias[c + j]);
        if (RELU) o[j] = fmaxf(o[j], 0.f);
    }
    uint2 st;
    *(__half2*)&st.x = __floats2half2_rn(o[0], o[1]);
    *(__half2*)&st.y = __floats2half2_rn(o[2], o[3]);
    *(uint2*)&outH[(size_t)node * 256 + c] = st;
}

// F=64 final layer, fp32 out
__global__ void __launch_bounds__(256) agg64(const __half* __restrict__ hw,
                                             const float* __restrict__ bias,
                                             float* __restrict__ out)
{
    int node = (blockIdx.x * blockDim.x + threadIdx.x) >> 5;
    const int lane = threadIdx.x & 31;
    const int c = lane * 2;
    const int r0 = g_rowptr[node], r1 = g_rowptr[node + 1];
    const float di = g_dinv[node];

    float ax = 0.f, ay = 0.f;
    int sc = g_col[r0];
    for (int e = r0; e < r1; e++) {
        int s = sc;
        if (e + 1 < r1) sc = g_col[e + 1];
        float w = g_dinv[s];
        float2 f = __half22float2(*(const __half2*)&hw[(size_t)s * 64 + c]);
        ax = fmaf(w, f.x, ax);
        ay = fmaf(w, f.y, ay);
    }
    float2 o;
    o.x = fmaf(di, ax, bias[c]);
    o.y = fmaf(di, ay, bias[c + 1]);
    *(float2*)&out[(size_t)node * 64 + c] = o;
}

// ---------------- launch (single stream; graph-capture safe) ----------------
extern "C" void kernel_launch(void* const* d_in, const int* in_sizes, int n_in,
                              void* d_out, int out_size)
{
    const float* x    = (const float*)d_in[0];
    const int*   ei   = (const int*)d_in[1];
    const float* pe_w = (const float*)d_in[2];
    const float* pe_b = (const float*)d_in[3];
    const float* ipw  = (const float*)d_in[4];
    const float* ipb  = (const float*)d_in[5];
    const float* opw  = (const float*)d_in[6];
    const float* opb  = (const float*)d_in[7];
    const float* w1   = (const float*)d_in[8];
    const float* b1   = (const float*)d_in[9];
    const float* w2   = (const float*)d_in[10];
    const float* b2   = (const float*)d_in[11];
    const float* w3   = (const float*)d_in[12];
    const float* b3   = (const float*)d_in[13];
    float* out = (float*)d_out;

    __half *hcatH, *t2H, *Bc, *Bw1, *Bw2, *Bw3, *t1h, *Qh, *Kh, *Vh;
    float *bc, *cvec, *zero;
    cudaGetSymbolAddress((void**)&hcatH, g_hcatH);
    cudaGetSymbolAddress((void**)&t2H,   g_t2H);
    cudaGetSymbolAddress((void**)&Bc,    g_Bc);
    cudaGetSymbolAddress((void**)&Bw1,   g_Bw1);
    cudaGetSymbolAddress((void**)&Bw2,   g_Bw2);
    cudaGetSymbolAddress((void**)&Bw3,   g_Bw3);
    cudaGetSymbolAddress((void**)&Qh,    g_Qh);
    cudaGetSymbolAddress((void**)&Kh,    g_Kh);
    cudaGetSymbolAddress((void**)&Vh,    g_Vh);
    cudaGetSymbolAddress((void**)&t1h,   g_t1h);
    cudaGetSymbolAddress((void**)&bc,    g_bc);
    cudaGetSymbolAddress((void**)&cvec,  g_cvec);
    cudaGetSymbolAddress((void**)&zero,  g_zero);

    prep<<<3138, 256>>>(x, w1, w2, w3, pe_w, ipw, opw, opb, pe_b, ipb, ei);
    k_scan<<<1, 1024>>>();
    k_fill<<<TE / 2048, 256>>>(ei);

    // qkv = x @ Wc + bc -> Q/K/V (f16); reads hcat x-cols (K=256, lda=320)
    gemm_mma<128, 2><<<dim3(NN / 128, 3), 256>>>(hcatH, Bc, bc, nullptr,
                                                 256, 320, 0, Qh, Kh, Vh);
    attn_mma<<<dim3(NN / QTILE, NH), 256>>>(Qh, Kh, Vh, hcatH);

    // GCN stack (out_proj folded into w1; +opb via cvec pre-aggregation)
    gemm_mma<128, 0><<<dim3(NN / 128, 4), 256>>>(hcatH, Bw1, nullptr, t1h,
                                                 320, 320, 256, nullptr, nullptr, nullptr);
    agg256<true><<<NN * 64 / 256, 256>>>(t1h, b1, cvec, t2H);
    gemm_mma<128, 0><<<dim3(NN / 128, 4), 256>>>(t2H, Bw2, nullptr, t1h,
                                                 256, 256, 256, nullptr, nullptr, nullptr);
    agg256<true><<<NN * 64 / 256, 256>>>(t1h, b2, zero, t2H);
    gemm_mma<64, 0><<<dim3(NN / 64, 1), 256>>>(t2H, Bw3, nullptr, t1h,
                                               256, 256, 64, nullptr, nullptr, nullptr);
    agg64<<<NN * 32 / 256, 256>>>(t1h, b3, out);
}